// round 2
// baseline (speedup 1.0000x reference)
#include <cuda_runtime.h>

#define BB 2048
#define CC 64
#define KK 512
#define NN 512
#define TM 32
#define TN 128
#define TK 32
#define XS_STRIDE 36   // padded row stride (floats) for Xs, keeps 16B alignment + spreads banks

__device__ int g_off[CC + 1];
__device__ int g_ids[BB];

// ---------------------------------------------------------------------------
// Kernel 1: counting-sort samples by expert index.
// Handles both int32 and int64 index buffers: if the data is int64, every odd
// 32-bit word is 0 (values are 0..63); if int32, odd words are random values
// and almost surely nonzero. We only read the first 2048 words (8 KB), which
// is within bounds for either dtype.
// ---------------------------------------------------------------------------
__global__ void bucket_kernel(const void* __restrict__ idx_raw) {
    __shared__ int s_cnt[CC];
    __shared__ int s_cur[CC];
    __shared__ int s_flag;
    const int tid = threadIdx.x;

    if (tid == 0) s_flag = 0;
    if (tid < CC) s_cnt[tid] = 0;
    __syncthreads();

    const int* w32 = (const int*)idx_raw;
    int any = 0;
    for (int i = 1 + 2 * tid; i < BB; i += 2 * blockDim.x) any |= w32[i];
    if (any) atomicOr(&s_flag, 1);
    __syncthreads();

    const bool is64 = (s_flag == 0);
    const long long* w64 = (const long long*)idx_raw;

    for (int i = tid; i < BB; i += blockDim.x) {
        int c = is64 ? (int)w64[i] : w32[i];
        atomicAdd(&s_cnt[c], 1);
    }
    __syncthreads();

    if (tid == 0) {
        int acc = 0;
        for (int c = 0; c < CC; c++) {
            g_off[c] = acc;
            s_cur[c] = acc;
            acc += s_cnt[c];
        }
        g_off[CC] = acc;
    }
    __syncthreads();

    for (int i = tid; i < BB; i += blockDim.x) {
        int c = is64 ? (int)w64[i] : w32[i];
        int pos = atomicAdd(&s_cur[c], 1);
        g_ids[pos] = i;
    }
}

// ---------------------------------------------------------------------------
// Kernel 2: per-(class, n-tile) grouped GEMM, fp32 FFMA.
// CTA: 128 threads. Tile: TM=32 samples x TN=128 outputs, K-tiled by 32.
// Thread micro-tile: 4 (m) x 8 (n) accumulators.
// blockIdx.x = class, blockIdx.y = n-tile (4), blockIdx.z = m-chunk slice.
// ---------------------------------------------------------------------------
__global__ __launch_bounds__(128) void gemm_kernel(
    const float* __restrict__ x,
    const float* __restrict__ weight,
    float* __restrict__ out)
{
    __shared__ float Ws[TK][TN];        // [k][n]
    __shared__ float Xs[TK][XS_STRIDE]; // [k][m], padded stride
    __shared__ int   s_rows[TM];

    const int c   = blockIdx.x;
    const int nt  = blockIdx.y;
    const int off = g_off[c];
    const int mc  = g_off[c + 1] - off;
    if (mc == 0) return;

    const float* wbase = weight + ((size_t)c * NN + (size_t)nt * TN) * KK;

    const int t  = threadIdx.x;
    const int tn = t & 15;   // 0..15 -> n group of 8
    const int tm = t >> 4;   // 0..7  -> m group of 4
    const int r  = t >> 2;   // 0..31 -> X load row
    const int q  = t & 3;    // k-quarter for X load

    for (int chunk = blockIdx.z; chunk * TM < mc; chunk += gridDim.z) {
        if (t < TM) {
            int m = chunk * TM + t;
            s_rows[t] = (m < mc) ? g_ids[off + m] : -1;
        }
        __syncthreads();

        float acc[4][8];
        #pragma unroll
        for (int i = 0; i < 4; i++)
            #pragma unroll
            for (int j = 0; j < 8; j++) acc[i][j] = 0.f;

        const int   row  = s_rows[r];
        const float* xrow = (row >= 0) ? (x + (size_t)row * KK) : x;

        #pragma unroll 1
        for (int kt = 0; kt < KK / TK; kt++) {
            const int k0 = kt * TK;

            // --- load W tile: thread t owns output row (nt*TN + t), 32 k's ---
            const float* wrow = wbase + (size_t)t * KK + k0;
            #pragma unroll
            for (int v = 0; v < 8; v++) {
                float4 f = *(const float4*)(wrow + v * 4);
                Ws[v * 4 + 0][t] = f.x;
                Ws[v * 4 + 1][t] = f.y;
                Ws[v * 4 + 2][t] = f.z;
                Ws[v * 4 + 3][t] = f.w;
            }

            // --- load X tile: thread handles sample-row r, k-quarter q ---
            {
                float4 f0 = make_float4(0.f, 0.f, 0.f, 0.f);
                float4 f1 = f0;
                if (row >= 0) {
                    const float* p = xrow + k0 + q * 8;
                    f0 = *(const float4*)p;
                    f1 = *(const float4*)(p + 4);
                }
                const int kk = q * 8;
                Xs[kk + 0][r] = f0.x;
                Xs[kk + 1][r] = f0.y;
                Xs[kk + 2][r] = f0.z;
                Xs[kk + 3][r] = f0.w;
                Xs[kk + 4][r] = f1.x;
                Xs[kk + 5][r] = f1.y;
                Xs[kk + 6][r] = f1.z;
                Xs[kk + 7][r] = f1.w;
            }
            __syncthreads();

            // --- compute: outer products over k ---
            #pragma unroll
            for (int k = 0; k < TK; k++) {
                float4 xv = *(const float4*)&Xs[k][tm * 4];
                float4 w0 = *(const float4*)&Ws[k][tn * 8];
                float4 w1 = *(const float4*)&Ws[k][tn * 8 + 4];
                float xf[4] = {xv.x, xv.y, xv.z, xv.w};
                float wf[8] = {w0.x, w0.y, w0.z, w0.w, w1.x, w1.y, w1.z, w1.w};
                #pragma unroll
                for (int i = 0; i < 4; i++)
                    #pragma unroll
                    for (int j = 0; j < 8; j++)
                        acc[i][j] = fmaf(xf[i], wf[j], acc[i][j]);
            }
            __syncthreads();
        }

        // --- epilogue ---
        #pragma unroll
        for (int i = 0; i < 4; i++) {
            const int m = tm * 4 + i;
            const int b = s_rows[m];
            if (b >= 0) {
                float* o = out + (size_t)b * NN + (size_t)nt * TN + tn * 8;
                float4 v0 = make_float4(acc[i][0], acc[i][1], acc[i][2], acc[i][3]);
                float4 v1 = make_float4(acc[i][4], acc[i][5], acc[i][6], acc[i][7]);
                *(float4*)o = v0;
                *(float4*)(o + 4) = v1;
            }
        }
        __syncthreads();  // protect s_rows before next chunk
    }
}

extern "C" void kernel_launch(void* const* d_in, const int* in_sizes, int n_in,
                              void* d_out, int out_size) {
    // Identify inputs by element count (all distinct): x=1048576, index=2048, weight=16777216
    const float* x = nullptr;
    const void*  idx = nullptr;
    const float* w = nullptr;
    for (int i = 0; i < n_in; i++) {
        if (in_sizes[i] == BB * KK)           x   = (const float*)d_in[i];
        else if (in_sizes[i] == BB)           idx = d_in[i];
        else if (in_sizes[i] == CC * NN * KK) w   = (const float*)d_in[i];
    }
    float* out = (float*)d_out;

    bucket_kernel<<<1, 256>>>(idx);
    dim3 grid(CC, NN / TN, 2);
    gemm_kernel<<<grid, 128>>>(x, w, out);
}

// round 3
// speedup vs baseline: 1.9965x; 1.9965x over previous
#include <cuda_runtime.h>

#define BB 2048
#define CC 64
#define KK 512
#define NN 512
#define TM 32
#define TN 128
#define TK 32
#define KHALF 256
#define XSTR 36

__device__ int   g_off[CC + 1];
__device__ int   g_ids[BB];
__device__ float g_partial[BB * NN];   // K-split partial sums (4 MB)

// ---------------------------------------------------------------------------
// Kernel 1: counting-sort samples by expert index (handles int32 or int64).
// ---------------------------------------------------------------------------
__global__ void bucket_kernel(const void* __restrict__ idx_raw) {
    __shared__ int s_cnt[CC];
    __shared__ int s_cur[CC];
    __shared__ int s_flag;
    const int tid = threadIdx.x;

    if (tid == 0) s_flag = 0;
    if (tid < CC) s_cnt[tid] = 0;
    __syncthreads();

    const int* w32 = (const int*)idx_raw;
    int any = 0;
    for (int i = 1 + 2 * tid; i < BB; i += 2 * blockDim.x) any |= w32[i];
    if (any) atomicOr(&s_flag, 1);
    __syncthreads();

    const bool is64 = (s_flag == 0);
    const long long* w64 = (const long long*)idx_raw;

    for (int i = tid; i < BB; i += blockDim.x) {
        int c = is64 ? (int)w64[i] : w32[i];
        atomicAdd(&s_cnt[c], 1);
    }
    __syncthreads();

    if (tid == 0) {
        int acc = 0;
        for (int c = 0; c < CC; c++) {
            g_off[c] = acc;
            s_cur[c] = acc;
            acc += s_cnt[c];
        }
        g_off[CC] = acc;
    }
    __syncthreads();

    for (int i = tid; i < BB; i += blockDim.x) {
        int c = is64 ? (int)w64[i] : w32[i];
        int pos = atomicAdd(&s_cur[c], 1);
        g_ids[pos] = i;
    }
}

// ---------------------------------------------------------------------------
// Kernel 2: grouped GEMM, fp32 FFMA, K-split + register-prefetch double buffer.
// grid = (class=64, ntile=4, z=4) where z = khalf*2 + chunkslice.
// CTA 128 threads, tile M=32 x N=128, K-chunk 32, micro-tile 4m x 8n.
// khalf 0 writes d_out; khalf 1 writes g_partial; add_kernel merges.
// ---------------------------------------------------------------------------
__global__ __launch_bounds__(128, 4) void gemm_kernel(
    const float* __restrict__ x,
    const float* __restrict__ weight,
    float* __restrict__ out)
{
    __shared__ float Ws[TK][TN];        // 16 KB, [k][n]
    __shared__ float Xs[TK][XSTR];      // [k][m], padded stride
    __shared__ int   s_rows[TM];

    const int c   = blockIdx.x;
    const int nt  = blockIdx.y;
    const int kh  = blockIdx.z >> 1;    // K half: 0 or 1
    const int cs  = blockIdx.z & 1;     // chunk slice
    const int off = g_off[c];
    const int mc  = g_off[c + 1] - off;
    if (mc == 0) return;

    const int k_base = kh * KHALF;
    const float* wbase = weight + ((size_t)c * NN + (size_t)nt * TN) * KK + k_base;
    float* obase = kh ? g_partial : out;

    const int t  = threadIdx.x;
    const int tn = t & 15;   // n group of 8
    const int tm = t >> 4;   // m group of 4
    const int r  = t >> 2;   // X sample row 0..31
    const int q  = t & 3;    // X k-quarter

    for (int chunk = cs; chunk * TM < mc; chunk += 2) {
        __syncthreads();    // protect s_rows from prior-iteration readers
        if (t < TM) {
            int m = chunk * TM + t;
            s_rows[t] = (m < mc) ? g_ids[off + m] : -1;
        }
        __syncthreads();

        const int row = s_rows[r];
        const float* xrow = x + (size_t)((row >= 0) ? row : 0) * KK + k_base;

        float acc[4][8];
        #pragma unroll
        for (int i = 0; i < 4; i++)
            #pragma unroll
            for (int j = 0; j < 8; j++) acc[i][j] = 0.f;

        // ---- prefetch tile 0 into registers ----
        const float* wp = wbase + (size_t)t * KK;
        float4 wreg[8];
        #pragma unroll
        for (int v = 0; v < 8; v++) wreg[v] = *(const float4*)(wp + v * 4);
        float4 xr0 = *(const float4*)(xrow + q * 8);
        float4 xr1 = *(const float4*)(xrow + q * 8 + 4);

        #pragma unroll 1
        for (int kt = 0; kt < KHALF / TK; kt++) {
            // ---- commit prefetched tile to smem ----
            #pragma unroll
            for (int v = 0; v < 8; v++) {
                Ws[v * 4 + 0][t] = wreg[v].x;
                Ws[v * 4 + 1][t] = wreg[v].y;
                Ws[v * 4 + 2][t] = wreg[v].z;
                Ws[v * 4 + 3][t] = wreg[v].w;
            }
            {
                const int kk = q * 8;
                Xs[kk + 0][r] = xr0.x; Xs[kk + 1][r] = xr0.y;
                Xs[kk + 2][r] = xr0.z; Xs[kk + 3][r] = xr0.w;
                Xs[kk + 4][r] = xr1.x; Xs[kk + 5][r] = xr1.y;
                Xs[kk + 6][r] = xr1.z; Xs[kk + 7][r] = xr1.w;
            }
            __syncthreads();

            // ---- issue prefetch for next tile (overlaps with compute) ----
            if (kt < KHALF / TK - 1) {
                const float* wpn = wp + (kt + 1) * TK;
                #pragma unroll
                for (int v = 0; v < 8; v++) wreg[v] = *(const float4*)(wpn + v * 4);
                const float* xp = xrow + (kt + 1) * TK + q * 8;
                xr0 = *(const float4*)xp;
                xr1 = *(const float4*)(xp + 4);
            }

            // ---- compute: 32 FFMA per k, 32 k ----
            #pragma unroll
            for (int k = 0; k < TK; k++) {
                float4 xv = *(const float4*)&Xs[k][tm * 4];
                float4 w0 = *(const float4*)&Ws[k][tn * 8];
                float4 w1 = *(const float4*)&Ws[k][tn * 8 + 4];
                float xf[4] = {xv.x, xv.y, xv.z, xv.w};
                float wf[8] = {w0.x, w0.y, w0.z, w0.w, w1.x, w1.y, w1.z, w1.w};
                #pragma unroll
                for (int i = 0; i < 4; i++)
                    #pragma unroll
                    for (int j = 0; j < 8; j++)
                        acc[i][j] = fmaf(xf[i], wf[j], acc[i][j]);
            }
            __syncthreads();
        }

        // ---- epilogue ----
        #pragma unroll
        for (int i = 0; i < 4; i++) {
            const int m = tm * 4 + i;
            const int b = s_rows[m];
            if (b >= 0) {
                float* o = obase + (size_t)b * NN + (size_t)nt * TN + tn * 8;
                *(float4*)o       = make_float4(acc[i][0], acc[i][1], acc[i][2], acc[i][3]);
                *(float4*)(o + 4) = make_float4(acc[i][4], acc[i][5], acc[i][6], acc[i][7]);
            }
        }
    }
}

// ---------------------------------------------------------------------------
// Kernel 3: out += partial (merge the two K halves). 1M floats.
// ---------------------------------------------------------------------------
__global__ void add_kernel(float* __restrict__ out) {
    const float4* p = (const float4*)g_partial;
    float4* o = (float4*)out;
    const int n4 = BB * NN / 4;
    for (int j = blockIdx.x * blockDim.x + threadIdx.x; j < n4;
         j += gridDim.x * blockDim.x) {
        float4 a = o[j];
        float4 b = p[j];
        a.x += b.x; a.y += b.y; a.z += b.z; a.w += b.w;
        o[j] = a;
    }
}

extern "C" void kernel_launch(void* const* d_in, const int* in_sizes, int n_in,
                              void* d_out, int out_size) {
    const float* x = nullptr;
    const void*  idx = nullptr;
    const float* w = nullptr;
    for (int i = 0; i < n_in; i++) {
        if (in_sizes[i] == BB * KK)           x   = (const float*)d_in[i];
        else if (in_sizes[i] == BB)           idx = d_in[i];
        else if (in_sizes[i] == CC * NN * KK) w   = (const float*)d_in[i];
    }
    float* out = (float*)d_out;

    bucket_kernel<<<1, 256>>>(idx);
    dim3 grid(CC, NN / TN, 4);
    gemm_kernel<<<grid, 128>>>(x, w, out);
    add_kernel<<<512, 256>>>(out);
}